// round 10
// baseline (speedup 1.0000x reference)
#include <cuda_runtime.h>
#include <mma.h>
#include <math.h>
#include <stdint.h>

using namespace nvcuda;

#define S_TOK 8192
#define MDIM  1024
#define HDIM  4096
#define NEXP  8
#define CAP   1024   // S/E, capacity 1.0, k=1

// ---------------- scratch (__device__ globals; no runtime alloc allowed) ----
// Referenced ONLY from device code (host-side symbol address is a stub — UB).
__device__ __align__(256) int   g_eidx[S_TOK];
__device__ __align__(256) float g_gval[S_TOK];
__device__ __align__(256) int   g_slot_token[NEXP * CAP];
__device__ __align__(256) float g_slot_gate[NEXP * CAP];
__device__ __align__(256) float g_h[(size_t)NEXP * CAP * HDIM];   // 128 MB hidden
__device__ __align__(256) float g_y[(size_t)NEXP * CAP * MDIM];   //  32 MB expert outputs

// ------------------------------- helpers -----------------------------------
__device__ __forceinline__ float gelu_exact(float v) {
    return 0.5f * v * (1.0f + erff(v * 0.70710678118654752440f));
}

// ---------------------------------------------------------------------------
// Gate: logits = x @ wg; softmax; argmax.   (proven)
// ---------------------------------------------------------------------------
__global__ __launch_bounds__(256)
void gate_kernel(const float* __restrict__ x, const float* __restrict__ wg) {
    __shared__ float swg[MDIM * NEXP];
    for (int i = threadIdx.x; i < MDIM * NEXP; i += blockDim.x) swg[i] = wg[i];
    __syncthreads();

    int warp = threadIdx.x >> 5;
    int lane = threadIdx.x & 31;
    int s = blockIdx.x * 8 + warp;
    if (s >= S_TOK) return;

    const float* xr = x + (size_t)s * MDIM;
    float acc[NEXP];
#pragma unroll
    for (int e = 0; e < NEXP; e++) acc[e] = 0.f;

    for (int k = lane; k < MDIM; k += 32) {
        float xv = xr[k];
#pragma unroll
        for (int e = 0; e < NEXP; e++) acc[e] += xv * swg[k * NEXP + e];
    }
#pragma unroll
    for (int e = 0; e < NEXP; e++) {
#pragma unroll
        for (int o = 16; o > 0; o >>= 1) acc[e] += __shfl_xor_sync(0xFFFFFFFFu, acc[e], o);
    }
    if (lane == 0) {
        float mx = acc[0];
        int mi = 0;
#pragma unroll
        for (int e = 1; e < NEXP; e++) {
            if (acc[e] > mx) { mx = acc[e]; mi = e; }
        }
        float den = 0.f;
#pragma unroll
        for (int e = 0; e < NEXP; e++) den += expf(acc[e] - mx);
        g_eidx[s] = mi;
        g_gval[s] = 1.0f / den;
    }
}

// ---------------------------------------------------------------------------
// Scan: exact in-order per-expert positions + capacity drop. (proven)
// ---------------------------------------------------------------------------
__global__ __launch_bounds__(256)
void scan_kernel() {
    __shared__ int cnt[256][NEXP + 1];
    int tid = threadIdx.x;

    for (int i = tid; i < NEXP * CAP; i += 256) {
        g_slot_token[i] = -1;
        g_slot_gate[i]  = 0.f;
    }

    int local[NEXP];
#pragma unroll
    for (int e = 0; e < NEXP; e++) local[e] = 0;

    int base = tid * 32;
    for (int t = 0; t < 32; t++) local[g_eidx[base + t]]++;
#pragma unroll
    for (int e = 0; e < NEXP; e++) cnt[tid][e] = local[e];
    __syncthreads();

    for (int off = 1; off < 256; off <<= 1) {
        int add[NEXP];
        if (tid >= off) {
#pragma unroll
            for (int e = 0; e < NEXP; e++) add[e] = cnt[tid - off][e];
        }
        __syncthreads();
        if (tid >= off) {
#pragma unroll
            for (int e = 0; e < NEXP; e++) cnt[tid][e] += add[e];
        }
        __syncthreads();
    }

    int run[NEXP];
#pragma unroll
    for (int e = 0; e < NEXP; e++) run[e] = cnt[tid][e] - local[e];

    for (int t = 0; t < 32; t++) {
        int s = base + t;
        int e = g_eidx[s];
        int p = run[e]++;
        if (p < CAP) {
            g_slot_token[e * CAP + p] = s;
            g_slot_gate[e * CAP + p]  = g_gval[s];
        }
    }
}

// ---------------------------------------------------------------------------
__global__ void zero_out_kernel(float4* __restrict__ out, int n4) {
    int i = blockIdx.x * blockDim.x + threadIdx.x;
    if (i < n4) out[i] = make_float4(0.f, 0.f, 0.f, 0.f);
}

// ---------------------------------------------------------------------------
// WMMA tf32 GEMM, double-buffered smem (static, 42KB), K-tile 16.
// Loop: fetch(regs) -> compute(stage t) -> commit(STS stage t+1) -> 1 sync.
// CTA tile 128x128, 8 warps, warp tile 32x64 (2x4 16x16 frags), 2 CTAs/SM.
// GATHER=true : A rows gathered from x (arg) via slot_token; C -> g_h (internal)
// GATHER=false: A = g_h (internal); C -> g_y (internal)
// ---------------------------------------------------------------------------
#define A_LD 24     // 16 + 8 pad (96 B, mult of 32 B for wmma)
#define B_LD 136    // 128 + 8 pad (544 B, mult of 32 B)

template <int KDIM, int NTOT, bool GATHER>
__global__ __launch_bounds__(256, 2)
void wmma_gemm_kernel(const float* __restrict__ Xin,   // x (harness ptr); used iff GATHER
                      const float* __restrict__ Bw) {  // weights [E][KDIM][NTOT] (harness ptr)
    __shared__ __align__(32) float As[2][128][A_LD];   // 2 x 12 KB
    __shared__ __align__(32) float Bs[2][16][B_LD];    // 2 x 8.5 KB

    const int tid  = threadIdx.x;
    const int e    = blockIdx.y >> 3;
    const int row0 = (blockIdx.y & 7) * 128;
    const int n0   = blockIdx.x * 128;

    // A loader: 2 threads/row, 8 floats (2x float4) each
    const int ar = tid >> 1;                 // 0..127
    const int ac = (tid & 1) * 8;            // 0 or 8
    const float* a_row;
    if constexpr (GATHER) {
        int tok = g_slot_token[e * CAP + row0 + ar];
        a_row = (tok >= 0) ? (Xin + (size_t)tok * KDIM) : nullptr;
    } else {
        a_row = g_h + (size_t)(e * CAP + row0 + ar) * KDIM;   // device-side ref
    }

    // B loader: 16 threads/row, 8 floats (2x float4) each
    const int br = tid >> 4;                 // 0..15
    const int bc = (tid & 15) * 8;           // 0..120
    const float* b_row = Bw + (size_t)e * KDIM * NTOT + n0 + bc;

    const int wid = tid >> 5;
    const int wm  = (wid & 3) * 32;
    const int wn  = (wid >> 2) * 64;

    wmma::fragment<wmma::accumulator, 16, 16, 8, float> acc[2][4];
#pragma unroll
    for (int mm = 0; mm < 2; mm++)
#pragma unroll
        for (int nn = 0; nn < 4; nn++) wmma::fill_fragment(acc[mm][nn], 0.f);

    float4 aR0, aR1, bR0, bR1;
    auto fetch = [&](int kt) {
        if (a_row) {
            aR0 = *(const float4*)(a_row + kt + ac);
            aR1 = *(const float4*)(a_row + kt + ac + 4);
        } else {
            aR0 = make_float4(0.f, 0.f, 0.f, 0.f);
            aR1 = aR0;
        }
        const float* bp = b_row + (size_t)(kt + br) * NTOT;
        bR0 = *(const float4*)(bp);
        bR1 = *(const float4*)(bp + 4);
    };
    auto commit = [&](int s) {
        As[s][ar][ac + 0] = wmma::__float_to_tf32(aR0.x);
        As[s][ar][ac + 1] = wmma::__float_to_tf32(aR0.y);
        As[s][ar][ac + 2] = wmma::__float_to_tf32(aR0.z);
        As[s][ar][ac + 3] = wmma::__float_to_tf32(aR0.w);
        As[s][ar][ac + 4] = wmma::__float_to_tf32(aR1.x);
        As[s][ar][ac + 5] = wmma::__float_to_tf32(aR1.y);
        As[s][ar][ac + 6] = wmma::__float_to_tf32(aR1.z);
        As[s][ar][ac + 7] = wmma::__float_to_tf32(aR1.w);
        Bs[s][br][bc + 0] = wmma::__float_to_tf32(bR0.x);
        Bs[s][br][bc + 1] = wmma::__float_to_tf32(bR0.y);
        Bs[s][br][bc + 2] = wmma::__float_to_tf32(bR0.z);
        Bs[s][br][bc + 3] = wmma::__float_to_tf32(bR0.w);
        Bs[s][br][bc + 4] = wmma::__float_to_tf32(bR1.x);
        Bs[s][br][bc + 5] = wmma::__float_to_tf32(bR1.y);
        Bs[s][br][bc + 6] = wmma::__float_to_tf32(bR1.z);
        Bs[s][br][bc + 7] = wmma::__float_to_tf32(bR1.w);
    };

    fetch(0);
    commit(0);
    __syncthreads();

    const int NT = KDIM / 16;
    for (int t = 0; t < NT; t++) {
        if (t + 1 < NT) fetch((t + 1) * 16);       // LDG issued before compute

        const int s = t & 1;
#pragma unroll
        for (int k8 = 0; k8 < 2; k8++) {
            wmma::fragment<wmma::matrix_a, 16, 16, 8, wmma::precision::tf32, wmma::row_major> af[2];
            wmma::fragment<wmma::matrix_b, 16, 16, 8, wmma::precision::tf32, wmma::row_major> bf[4];
#pragma unroll
            for (int mm = 0; mm < 2; mm++)
                wmma::load_matrix_sync(af[mm], &As[s][wm + mm * 16][k8 * 8], A_LD);
#pragma unroll
            for (int nn = 0; nn < 4; nn++)
                wmma::load_matrix_sync(bf[nn], &Bs[s][k8 * 8][wn + nn * 16], B_LD);
#pragma unroll
            for (int mm = 0; mm < 2; mm++)
#pragma unroll
                for (int nn = 0; nn < 4; nn++)
                    wmma::mma_sync(acc[mm][nn], af[mm], bf[nn], acc[mm][nn]);
        }

        if (t + 1 < NT) commit((t + 1) & 1);       // STS into the other stage
        __syncthreads();                           // one sync per iteration
    }

    // ---- store raw C to the internal scratch for this GEMM ----
    float* Cbase = GATHER ? g_h : g_y;       // device-side reference
#pragma unroll
    for (int mm = 0; mm < 2; mm++) {
        float* crow = Cbase + (size_t)(e * CAP + row0 + wm + mm * 16) * NTOT + n0 + wn;
#pragma unroll
        for (int nn = 0; nn < 4; nn++)
            wmma::store_matrix_sync(crow + nn * 16, acc[mm][nn], NTOT, wmma::mem_row_major);
    }
}

// ---------------------------------------------------------------------------
// Elementwise: g_h = gelu(g_h + b1[e])
// ---------------------------------------------------------------------------
__global__ __launch_bounds__(256)
void gelu_bias_kernel(const float* __restrict__ b1) {
    int row = blockIdx.x;                 // 0..8191  (= e*CAP + c)
    int e   = row >> 10;
    float* hp = g_h + (size_t)row * HDIM;
    const float* bp = b1 + e * HDIM;
    for (int j = threadIdx.x; j < HDIM / 4; j += 256) {
        float4 v = ((const float4*)hp)[j];
        float4 b = ((const float4*)bp)[j];
        v.x = gelu_exact(v.x + b.x);
        v.y = gelu_exact(v.y + b.y);
        v.z = gelu_exact(v.z + b.z);
        v.w = gelu_exact(v.w + b.w);
        ((float4*)hp)[j] = v;
    }
}

// ---------------------------------------------------------------------------
// Combine: out[tok] = gate * (g_y[slot] + b2[e])   (dropped tokens stay 0)
// ---------------------------------------------------------------------------
__global__ __launch_bounds__(256)
void combine_kernel(const float* __restrict__ b2, float* __restrict__ out) {
    int slot = blockIdx.x;                // 0..8191
    int tok  = g_slot_token[slot];
    if (tok < 0) return;
    int e = slot >> 10;
    float gv = g_slot_gate[slot];
    const float* yp = g_y + (size_t)slot * MDIM;
    const float* bp = b2 + e * MDIM;
    float* op = out + (size_t)tok * MDIM;
    for (int j = threadIdx.x; j < MDIM / 4; j += 256) {
        float4 v = ((const float4*)yp)[j];
        float4 b = ((const float4*)bp)[j];
        v.x = gv * (v.x + b.x);
        v.y = gv * (v.y + b.y);
        v.z = gv * (v.z + b.z);
        v.w = gv * (v.w + b.w);
        ((float4*)op)[j] = v;
    }
}

// ---------------------------------------------------------------------------
extern "C" void kernel_launch(void* const* d_in, const int* in_sizes, int n_in,
                              void* d_out, int out_size) {
    const float* x   = (const float*)d_in[0];   // [S, M]
    const float* wg  = (const float*)d_in[1];   // [M, E]
    const float* w1  = (const float*)d_in[2];   // [E, M, H]
    const float* b1  = (const float*)d_in[3];   // [E, H]
    const float* w2  = (const float*)d_in[4];   // [E, H, M]
    const float* b2  = (const float*)d_in[5];   // [E, M]
    float* out = (float*)d_out;                 // [S, M]

    gate_kernel<<<S_TOK / 8, 256>>>(x, wg);
    scan_kernel<<<1, 256>>>();

    int n4 = (S_TOK * MDIM) / 4;
    zero_out_kernel<<<(n4 + 255) / 256, 256>>>((float4*)out, n4);

    // GEMM1: g_h(raw) = gathered_x @ W1   (A from x arg; C -> g_h internal)
    wmma_gemm_kernel<MDIM, HDIM, true><<<dim3(HDIM / 128, NEXP * 8), 256>>>(x, w1);
    // g_h = gelu(g_h + b1)
    gelu_bias_kernel<<<NEXP * CAP, 256>>>(b1);
    // GEMM2: g_y(raw) = g_h @ W2          (A internal; C -> g_y internal)
    wmma_gemm_kernel<HDIM, MDIM, false><<<dim3(MDIM / 128, NEXP * 8), 256>>>(x, w2);
    // out[tok] = gate * (g_y + b2)
    combine_kernel<<<NEXP * CAP, 256>>>(b2, out);
}

// round 11
// speedup vs baseline: 1.3987x; 1.3987x over previous
#include <cuda_runtime.h>
#include <mma.h>
#include <math.h>
#include <stdint.h>

using namespace nvcuda;

#define S_TOK 8192
#define MDIM  1024
#define HDIM  4096
#define NEXP  8
#define CAP   1024   // S/E, capacity 1.0, k=1

// ---------------- scratch (__device__ globals; no runtime alloc allowed) ----
// Referenced ONLY from device code (host-side symbol address is a stub — UB).
__device__ __align__(256) int   g_eidx[S_TOK];
__device__ __align__(256) float g_gval[S_TOK];
__device__ __align__(256) int   g_slot_token[NEXP * CAP];
__device__ __align__(256) float g_slot_gate[NEXP * CAP];
__device__ __align__(256) float g_h[(size_t)NEXP * CAP * HDIM];   // 128 MB hidden (gelu'd)

// ------------------------------- helpers -----------------------------------
__device__ __forceinline__ float gelu_exact(float v) {
    return 0.5f * v * (1.0f + erff(v * 0.70710678118654752440f));
}

// ---------------------------------------------------------------------------
// Gate: logits = x @ wg; softmax; argmax.   (proven)
// ---------------------------------------------------------------------------
__global__ __launch_bounds__(256)
void gate_kernel(const float* __restrict__ x, const float* __restrict__ wg) {
    __shared__ float swg[MDIM * NEXP];
    for (int i = threadIdx.x; i < MDIM * NEXP; i += blockDim.x) swg[i] = wg[i];
    __syncthreads();

    int warp = threadIdx.x >> 5;
    int lane = threadIdx.x & 31;
    int s = blockIdx.x * 8 + warp;
    if (s >= S_TOK) return;

    const float* xr = x + (size_t)s * MDIM;
    float acc[NEXP];
#pragma unroll
    for (int e = 0; e < NEXP; e++) acc[e] = 0.f;

    for (int k = lane; k < MDIM; k += 32) {
        float xv = xr[k];
#pragma unroll
        for (int e = 0; e < NEXP; e++) acc[e] += xv * swg[k * NEXP + e];
    }
#pragma unroll
    for (int e = 0; e < NEXP; e++) {
#pragma unroll
        for (int o = 16; o > 0; o >>= 1) acc[e] += __shfl_xor_sync(0xFFFFFFFFu, acc[e], o);
    }
    if (lane == 0) {
        float mx = acc[0];
        int mi = 0;
#pragma unroll
        for (int e = 1; e < NEXP; e++) {
            if (acc[e] > mx) { mx = acc[e]; mi = e; }
        }
        float den = 0.f;
#pragma unroll
        for (int e = 0; e < NEXP; e++) den += expf(acc[e] - mx);
        g_eidx[s] = mi;
        g_gval[s] = 1.0f / den;
    }
}

// ---------------------------------------------------------------------------
// Scan: exact in-order per-expert positions + capacity drop. (proven)
// ---------------------------------------------------------------------------
__global__ __launch_bounds__(256)
void scan_kernel() {
    __shared__ int cnt[256][NEXP + 1];
    int tid = threadIdx.x;

    for (int i = tid; i < NEXP * CAP; i += 256) {
        g_slot_token[i] = -1;
        g_slot_gate[i]  = 0.f;
    }

    int local[NEXP];
#pragma unroll
    for (int e = 0; e < NEXP; e++) local[e] = 0;

    int base = tid * 32;
    for (int t = 0; t < 32; t++) local[g_eidx[base + t]]++;
#pragma unroll
    for (int e = 0; e < NEXP; e++) cnt[tid][e] = local[e];
    __syncthreads();

    for (int off = 1; off < 256; off <<= 1) {
        int add[NEXP];
        if (tid >= off) {
#pragma unroll
            for (int e = 0; e < NEXP; e++) add[e] = cnt[tid - off][e];
        }
        __syncthreads();
        if (tid >= off) {
#pragma unroll
            for (int e = 0; e < NEXP; e++) cnt[tid][e] += add[e];
        }
        __syncthreads();
    }

    int run[NEXP];
#pragma unroll
    for (int e = 0; e < NEXP; e++) run[e] = cnt[tid][e] - local[e];

    for (int t = 0; t < 32; t++) {
        int s = base + t;
        int e = g_eidx[s];
        int p = run[e]++;
        if (p < CAP) {
            g_slot_token[e * CAP + p] = s;
            g_slot_gate[e * CAP + p]  = g_gval[s];
        }
    }
}

// ---------------------------------------------------------------------------
__global__ void zero_out_kernel(float4* __restrict__ out, int n4) {
    int i = blockIdx.x * blockDim.x + threadIdx.x;
    if (i < n4) out[i] = make_float4(0.f, 0.f, 0.f, 0.f);
}

// ---------------------------------------------------------------------------
// WMMA tf32 GEMM — mainloop identical to round-9 (best measured: 2389us).
// CTA tile 128x128, K-tile 32, single smem stage, 8 warps, 2 CTAs/SM.
// NEW: fused epilogue via per-warp smem staging of acc fragments:
//   GATHER=true : g_h = gelu(acc + b1)        (was: raw store + separate pass)
//   GATHER=false: out[tok] = gate*(acc + b2)  (was: g_y + separate combine)
// ---------------------------------------------------------------------------
#define A_LD 40     // 160 B row stride (mult of 32 B for wmma)
#define B_LD 136    // 544 B row stride (mult of 32 B)

template <int KDIM, int NTOT, bool GATHER>
__global__ __launch_bounds__(256, 2)
void wmma_gemm_kernel(const float* __restrict__ Xin,   // x (harness ptr); used iff GATHER
                      const float* __restrict__ Bw,    // weights [E][KDIM][NTOT]
                      const float* __restrict__ bias,  // [E][NTOT]
                      float* __restrict__ outp) {      // d_out; used iff !GATHER
    __shared__ __align__(32) float As[128][A_LD];
    __shared__ __align__(32) float Bs[32][B_LD];

    const int tid  = threadIdx.x;
    const int e    = blockIdx.y >> 3;
    const int row0 = (blockIdx.y & 7) * 128;
    const int n0   = blockIdx.x * 128;

    // A loader: 2 threads per row, 16 floats (4x float4) each
    const int ar = tid >> 1;                 // 0..127
    const int ac = (tid & 1) * 16;           // 0 or 16
    const float* a_row;
    if constexpr (GATHER) {
        int tok = g_slot_token[e * CAP + row0 + ar];
        a_row = (tok >= 0) ? (Xin + (size_t)tok * KDIM) : nullptr;
    } else {
        a_row = g_h + (size_t)(e * CAP + row0 + ar) * KDIM;   // device-side ref
    }

    // B loader: 8 threads per row, 16 floats each
    const int br = tid >> 3;                 // 0..31
    const int bc = (tid & 7) * 16;           // 0..112
    const float* b_row = Bw + (size_t)e * KDIM * NTOT + n0 + bc;

    const int wid = tid >> 5;
    const int wm  = (wid & 3) * 32;
    const int wn  = (wid >> 2) * 64;

    wmma::fragment<wmma::accumulator, 16, 16, 8, float> acc[2][4];
#pragma unroll
    for (int mm = 0; mm < 2; mm++)
#pragma unroll
        for (int nn = 0; nn < 4; nn++) wmma::fill_fragment(acc[mm][nn], 0.f);

    for (int kt = 0; kt < KDIM; kt += 32) {
        // ---- load tile straight to smem (latency hidden by co-resident CTA) ----
        if (a_row) {
#pragma unroll
            for (int i = 0; i < 4; i++) {
                float4 v = *(const float4*)(a_row + kt + ac + i * 4);
                As[ar][ac + i * 4 + 0] = wmma::__float_to_tf32(v.x);
                As[ar][ac + i * 4 + 1] = wmma::__float_to_tf32(v.y);
                As[ar][ac + i * 4 + 2] = wmma::__float_to_tf32(v.z);
                As[ar][ac + i * 4 + 3] = wmma::__float_to_tf32(v.w);
            }
        } else {
#pragma unroll
            for (int i = 0; i < 4; i++) {
                As[ar][ac + i * 4 + 0] = 0.f;
                As[ar][ac + i * 4 + 1] = 0.f;
                As[ar][ac + i * 4 + 2] = 0.f;
                As[ar][ac + i * 4 + 3] = 0.f;
            }
        }
        {
            const float* bp = b_row + (size_t)(kt + br) * NTOT;
#pragma unroll
            for (int i = 0; i < 4; i++) {
                float4 v = *(const float4*)(bp + i * 4);
                Bs[br][bc + i * 4 + 0] = wmma::__float_to_tf32(v.x);
                Bs[br][bc + i * 4 + 1] = wmma::__float_to_tf32(v.y);
                Bs[br][bc + i * 4 + 2] = wmma::__float_to_tf32(v.z);
                Bs[br][bc + i * 4 + 3] = wmma::__float_to_tf32(v.w);
            }
        }
        __syncthreads();

#pragma unroll
        for (int k8 = 0; k8 < 4; k8++) {
            wmma::fragment<wmma::matrix_a, 16, 16, 8, wmma::precision::tf32, wmma::row_major> af[2];
            wmma::fragment<wmma::matrix_b, 16, 16, 8, wmma::precision::tf32, wmma::row_major> bf[4];
#pragma unroll
            for (int mm = 0; mm < 2; mm++)
                wmma::load_matrix_sync(af[mm], &As[wm + mm * 16][k8 * 8], A_LD);
#pragma unroll
            for (int nn = 0; nn < 4; nn++)
                wmma::load_matrix_sync(bf[nn], &Bs[k8 * 8][wn + nn * 16], B_LD);
#pragma unroll
            for (int mm = 0; mm < 2; mm++)
#pragma unroll
                for (int nn = 0; nn < 4; nn++)
                    wmma::mma_sync(acc[mm][nn], af[mm], bf[nn], acc[mm][nn]);
        }
        __syncthreads();
    }

    // ---------------- fused epilogue via per-warp smem staging --------------
    // After the loop-end __syncthreads all warps are done reading As/Bs, so
    // reuse As storage as per-warp 16x20 staging buffers (8 x 320 floats).
    float* stage = &As[0][0] + wid * 320;
    const int lane = tid & 31;
    const int r  = lane >> 1;                // staged row this thread handles
    const int cb = (lane & 1) * 8;           // 8 consecutive cols

#pragma unroll
    for (int mm = 0; mm < 2; mm++) {
        const int rowE = row0 + wm + mm * 16;
#pragma unroll
        for (int nn = 0; nn < 4; nn++) {
            wmma::store_matrix_sync(stage, acc[mm][nn], 20, wmma::mem_row_major);
            __syncwarp();
            const int col0 = n0 + wn + nn * 16;
            const float* bp = bias + (size_t)e * NTOT + col0;
            if constexpr (GATHER) {
                float* orow = g_h + (size_t)(e * CAP + rowE + r) * NTOT + col0;
#pragma unroll
                for (int i = 0; i < 8; i++) {
                    int c = cb + i;
                    orow[c] = gelu_exact(stage[r * 20 + c] + bp[c]);
                }
            } else {
                const int slotRow = e * CAP + rowE + r;
                const int tok = g_slot_token[slotRow];
                if (tok >= 0) {
                    const float gv = g_slot_gate[slotRow];
                    float* orow = outp + (size_t)tok * MDIM + col0;
#pragma unroll
                    for (int i = 0; i < 8; i++) {
                        int c = cb + i;
                        orow[c] = gv * (stage[r * 20 + c] + bp[c]);
                    }
                }
            }
            __syncwarp();                    // before next store overwrites stage
        }
    }
}

// ---------------------------------------------------------------------------
extern "C" void kernel_launch(void* const* d_in, const int* in_sizes, int n_in,
                              void* d_out, int out_size) {
    const float* x   = (const float*)d_in[0];   // [S, M]
    const float* wg  = (const float*)d_in[1];   // [M, E]
    const float* w1  = (const float*)d_in[2];   // [E, M, H]
    const float* b1  = (const float*)d_in[3];   // [E, H]
    const float* w2  = (const float*)d_in[4];   // [E, H, M]
    const float* b2  = (const float*)d_in[5];   // [E, M]
    float* out = (float*)d_out;                 // [S, M]

    gate_kernel<<<S_TOK / 8, 256>>>(x, wg);
    scan_kernel<<<1, 256>>>();

    int n4 = (S_TOK * MDIM) / 4;
    zero_out_kernel<<<(n4 + 255) / 256, 256>>>((float4*)out, n4);

    // GEMM1: g_h = gelu(gathered_x @ W1 + b1)   (fused epilogue)
    wmma_gemm_kernel<MDIM, HDIM, true><<<dim3(HDIM / 128, NEXP * 8), 256>>>(x, w1, b1, out);
    // GEMM2: out[tok] = gate * (g_h @ W2 + b2)  (fused scatter-combine)
    wmma_gemm_kernel<HDIM, MDIM, false><<<dim3(MDIM / 128, NEXP * 8), 256>>>(x, w2, b2, out);
}